// round 14
// baseline (speedup 1.0000x reference)
#include <cuda_runtime.h>

// Per-CTA software-pipelined 4-sample MLP: the sparse GEMV2 of sample k is
// interleaved in ONE loop with the dense GEMV1 of sample k+1, so decimated
// sparse loads are always mixed with dense streaming traffic (R12 measured
// isolated sparse GEMV2 at only 61% DRAM; mixed phases run at ~86%).
//   h = relu(x[b,:] @ w1[b,:,:] + b1[b,:])   (D=128 -> H=256)
//   out = h @ w2[b,:,:] + b2[b,:]            (H=256 -> C=64)
// w2 rows with h[j]==0 are never loaded (exact, ~50% skipped).
// Grid = 1024 CTAs x 128 thr -> single wave (>=7 CTAs/SM resident).

#define B_DIM 4096
#define D_DIM 128
#define H_DIM 256
#define C_DIM 64
#define SAMP  4

__global__ void __launch_bounds__(128, 8) mlp_pipe_kernel(
    const float* __restrict__ x,
    const float* __restrict__ w1,
    const float* __restrict__ b1,
    const float* __restrict__ w2,
    const float* __restrict__ b2,
    float* __restrict__ out)
{
    const int l  = threadIdx.x;            // 0..127
    const int b0 = blockIdx.x * SAMP;

    __shared__ float  x_s[SAMP][D_DIM];    // 2 KB: all 4 inputs
    __shared__ float  h_s[2][H_DIM];       // double-buffered activations
    __shared__ float4 part1[128];          // GEMV1 partials
    __shared__ float4 part2[128];          // GEMV2 partials

    // ---- stage all 4 x vectors (contiguous 2KB) ----
    reinterpret_cast<float4*>(&x_s[0][0])[l] =
        reinterpret_cast<const float4*>(x + (size_t)b0 * D_DIM)[l];
    __syncthreads();

    const int g     = l & 63;              // GEMV1 column group
    const int dbase = (l >> 6) * 64;       // GEMV1 d-range
    const int cg    = l & 15;              // GEMV2 column group
    const int jslot = l >> 4;              // GEMV2 row slot

    // ================= prologue: dense GEMV1 for sample 0 ==================
    {
        const float4* w1v = reinterpret_cast<const float4*>(
            w1 + (size_t)b0 * D_DIM * H_DIM);
        float4 acc = make_float4(0.f, 0.f, 0.f, 0.f);
        #pragma unroll
        for (int i = 0; i < 64; ++i) {
            const int d = dbase + i;
            const float  xv = x_s[0][d];
            const float4 w  = __ldcs(&w1v[d * (H_DIM / 4) + g]);
            acc.x = fmaf(xv, w.x, acc.x);
            acc.y = fmaf(xv, w.y, acc.y);
            acc.z = fmaf(xv, w.z, acc.z);
            acc.w = fmaf(xv, w.w, acc.w);
        }
        part1[l] = acc;
    }
    __syncthreads();
    if (l < 64) {
        float4 s0 = part1[l];
        float4 s1 = part1[64 + l];
        float4 bb = reinterpret_cast<const float4*>(b1 + (size_t)b0 * H_DIM)[l];
        float4 h4;
        h4.x = fmaxf(s0.x + s1.x + bb.x, 0.f);
        h4.y = fmaxf(s0.y + s1.y + bb.y, 0.f);
        h4.z = fmaxf(s0.z + s1.z + bb.z, 0.f);
        h4.w = fmaxf(s0.w + s1.w + bb.w, 0.f);
        reinterpret_cast<float4*>(h_s[0])[l] = h4;
    }
    __syncthreads();

    // ================= main pipeline over samples ==========================
    #pragma unroll 1
    for (int k = 0; k < SAMP; ++k) {
        const int cur = k & 1;
        const int bk  = b0 + k;

        // register activity mask for GEMV2(k): 32 independent LDS reads
        unsigned m = 0;
        #pragma unroll
        for (int i = 0; i < 32; ++i)
            m |= (h_s[cur][jslot + i * 8] > 0.f) ? (1u << i) : 0u;

        const float4* w2v = reinterpret_cast<const float4*>(
            w2 + (size_t)bk * H_DIM * C_DIM);
        float4 acc2 = make_float4(0.f, 0.f, 0.f, 0.f);

        if (k < SAMP - 1) {
            // ---- fused loop: GEMV1(k+1) dense + GEMV2(k) sparse ----
            const float4* w1v = reinterpret_cast<const float4*>(
                w1 + (size_t)(bk + 1) * D_DIM * H_DIM);
            float4 acc1 = make_float4(0.f, 0.f, 0.f, 0.f);
            #pragma unroll 16
            for (int i = 0; i < 64; ++i) {
                const int d = dbase + i;
                const float  xv = x_s[k + 1][d];
                const float4 w  = __ldcs(&w1v[d * (H_DIM / 4) + g]);
                acc1.x = fmaf(xv, w.x, acc1.x);
                acc1.y = fmaf(xv, w.y, acc1.y);
                acc1.z = fmaf(xv, w.z, acc1.z);
                acc1.w = fmaf(xv, w.w, acc1.w);
                if ((i & 1) == 0) {
                    const int ii = i >> 1;
                    if ((m >> ii) & 1u) {
                        const int j = jslot + ii * 8;
                        const float4 wv = __ldcs(&w2v[j * (C_DIM / 4) + cg]);
                        const float  hv = h_s[cur][j];
                        acc2.x = fmaf(hv, wv.x, acc2.x);
                        acc2.y = fmaf(hv, wv.y, acc2.y);
                        acc2.z = fmaf(hv, wv.z, acc2.z);
                        acc2.w = fmaf(hv, wv.w, acc2.w);
                    }
                }
            }
            part1[l] = acc1;
        } else {
            // ---- tail: last sample's GEMV2 alone ----
            #pragma unroll 16
            for (int ii = 0; ii < 32; ++ii) {
                if ((m >> ii) & 1u) {
                    const int j = jslot + ii * 8;
                    const float4 wv = __ldcs(&w2v[j * (C_DIM / 4) + cg]);
                    const float  hv = h_s[cur][j];
                    acc2.x = fmaf(hv, wv.x, acc2.x);
                    acc2.y = fmaf(hv, wv.y, acc2.y);
                    acc2.z = fmaf(hv, wv.z, acc2.z);
                    acc2.w = fmaf(hv, wv.w, acc2.w);
                }
            }
        }
        part2[l] = acc2;
        __syncthreads();

        // ---- reduces (disjoint warps, no internal barrier needed) ----
        if (l < 64 && k < SAMP - 1) {
            // h reduce for sample k+1 -> other h buffer
            float4 s0 = part1[l];
            float4 s1 = part1[64 + l];
            float4 bb = reinterpret_cast<const float4*>(
                b1 + (size_t)(bk + 1) * H_DIM)[l];
            float4 h4;
            h4.x = fmaxf(s0.x + s1.x + bb.x, 0.f);
            h4.y = fmaxf(s0.y + s1.y + bb.y, 0.f);
            h4.z = fmaxf(s0.z + s1.z + bb.z, 0.f);
            h4.w = fmaxf(s0.w + s1.w + bb.w, 0.f);
            reinterpret_cast<float4*>(h_s[(k + 1) & 1])[l] = h4;
        }
        if (l >= 64 && l < 80) {
            // out reduce for sample k
            const int t = l - 64;
            float4 acc = part2[t];
            #pragma unroll
            for (int kk = 1; kk < 8; ++kk) {
                float4 p = part2[kk * 16 + t];
                acc.x += p.x; acc.y += p.y; acc.z += p.z; acc.w += p.w;
            }
            float4 bb = reinterpret_cast<const float4*>(
                b2 + (size_t)bk * C_DIM)[t];
            acc.x += bb.x; acc.y += bb.y; acc.z += bb.z; acc.w += bb.w;
            __stcs(reinterpret_cast<float4*>(out + (size_t)bk * C_DIM) + t, acc);
        }
        __syncthreads();
    }
}

extern "C" void kernel_launch(void* const* d_in, const int* in_sizes, int n_in,
                              void* d_out, int out_size)
{
    const float* x  = (const float*)d_in[0];
    const float* w1 = (const float*)d_in[1];
    const float* b1 = (const float*)d_in[2];
    const float* w2 = (const float*)d_in[3];
    const float* b2 = (const float*)d_in[4];
    float* out = (float*)d_out;

    mlp_pipe_kernel<<<B_DIM / SAMP, 128>>>(x, w1, b1, w2, b2, out);
}